// round 4
// baseline (speedup 1.0000x reference)
#include <cuda_runtime.h>
#include <math.h>

#define HW 65536
#define WIDTH 256

__device__ float g_xn[(size_t)HW * 256];
__device__ float g_y[(size_t)HW * 256];
__device__ float g_h[(size_t)HW * 1024];
__device__ float g_mean[HW];
__device__ float g_rstd[HW];

#define LN1_SMEM ((256 * 65 + 128) * 4)
#define ATTN_SMEM ((4 * 64 * 129 + 128 * 65 + 128 * 64) * 4 + 64 * 4)
#define RES_SMEM (64 * 257 * 4)

// -------------------------------------------------------------- LN1
__global__ void __launch_bounds__(256) ln1_kernel(
    const float* __restrict__ x, const float* __restrict__ g1,
    const float* __restrict__ b1) {
    extern __shared__ float sm[];
    float* smean = sm + 256 * 65;
    float* srstd = smean + 64;
    const int tid = threadIdx.x;
    const int pbase = blockIdx.x * 64;
    for (int e = tid; e < 256 * 64; e += 256) {
        int c = e >> 6, p = e & 63;
        sm[c * 65 + p] = x[c * HW + pbase + p];
    }
    __syncthreads();
    if (tid < 64) {
        float s = 0.f, sq = 0.f;
        #pragma unroll 8
        for (int c = 0; c < 256; c++) {
            float v = sm[c * 65 + tid];
            s += v; sq += v * v;
        }
        float m = s * (1.f / 256.f);
        float var = sq * (1.f / 256.f) - m * m;
        smean[tid] = m;
        srstd[tid] = rsqrtf(var + 1e-5f);
    }
    __syncthreads();
    const float gc = g1[tid], bc = b1[tid];
    #pragma unroll 8
    for (int i = 0; i < 64; i++) {
        float v = sm[tid * 65 + i];
        g_xn[(size_t)(pbase + i) * 256 + tid] = (v - smean[i]) * srstd[i] * gc + bc;
    }
}

// -------------------------------------------------------------- Attention
__global__ void __launch_bounds__(256) attn_kernel(
    const float* __restrict__ qkv_r, const float* __restrict__ proj_r,
    const float* __restrict__ pb_r, const float* __restrict__ tab_r,
    const float* __restrict__ qkv_a, const float* __restrict__ proj_a,
    const float* __restrict__ pb_a, const float* __restrict__ tab_a) {
    extern __shared__ float sm[];
    float* Xs = sm;                    // 64 x 129
    float* Qb = Xs + 64 * 129;         // 64 x 129 (reused as O)
    float* Kb = Qb + 64 * 129;
    float* Vb = Kb + 64 * 129;
    float* Ss = Vb + 64 * 129;         // 128 x 65
    float* Wst = Ss + 128 * 65;        // 128 x 64
    int* tokp = (int*)(Wst + 128 * 64);

    const int tid = threadIdx.x;
    const int br = blockIdx.y;
    const float* qkvw = br ? qkv_a : qkv_r;
    const float* projw = br ? proj_a : proj_r;
    const float* projb = br ? pb_a : pb_r;
    const float* table = br ? tab_a : tab_r;
    const int coff = br ? 128 : 0;
    const int wwsh = br ? 4 : 2;
    const int Ww = 1 << wwsh;
    const int Wh = 64 >> wwsh;
    const int nWx = WIDTH >> wwsh;
    const int win = blockIdx.x;
    const int wy = win / nWx;
    const int wx = win - wy * nWx;
    const int row0 = wy * Wh, col0 = wx * Ww;

    if (tid < 64) {
        int ih = tid >> wwsh, iw = tid & (Ww - 1);
        tokp[tid] = (row0 + ih) * WIDTH + col0 + iw;
    }
    __syncthreads();
    for (int e = tid; e < 64 * 128; e += 256) {
        int t = e >> 7, c = e & 127;
        Xs[t * 129 + c] = g_xn[(size_t)tokp[t] * 256 + coff + c];
    }

    const int tm = tid & 15;
    const int tn4 = (tid >> 4) * 4;

    // QKV: 6 chunks of 64 output cols
    for (int cc = 0; cc < 6; cc++) {
        __syncthreads();
        for (int e = tid; e < 128 * 64; e += 256) {
            int k = e >> 6, n = e & 63;
            Wst[e] = qkvw[k * 384 + cc * 64 + n];
        }
        __syncthreads();
        float acc[4][4] = {};
        #pragma unroll 4
        for (int k = 0; k < 128; k++) {
            float a[4], b[4];
            #pragma unroll
            for (int r = 0; r < 4; r++) a[r] = Xs[(tm + 16 * r) * 129 + k];
            #pragma unroll
            for (int u = 0; u < 4; u++) b[u] = Wst[k * 64 + tn4 + u];
            #pragma unroll
            for (int r = 0; r < 4; r++)
                #pragma unroll
                for (int u = 0; u < 4; u++)
                    acc[r][u] = fmaf(a[r], b[u], acc[r][u]);
        }
        float* dst = (cc < 2) ? Qb : ((cc < 4) ? Kb : Vb);
        const int cb = (cc & 1) * 64;
        #pragma unroll
        for (int r = 0; r < 4; r++)
            #pragma unroll
            for (int u = 0; u < 4; u++)
                dst[(tm + 16 * r) * 129 + cb + tn4 + u] = acc[r][u];
    }
    __syncthreads();

    // scores + rel-pos bias
    {
        const int h = tid >> 7;
        const int rest = tid & 127;
        const int ti = rest & 15;
        const int tj8 = (rest >> 4) * 8;
        const int qo = h * 64;
        float acc[4][8] = {};
        #pragma unroll 4
        for (int d = 0; d < 64; d++) {
            float q[4], kv[8];
            #pragma unroll
            for (int r = 0; r < 4; r++) q[r] = Qb[(ti + 16 * r) * 129 + qo + d];
            #pragma unroll
            for (int u = 0; u < 8; u++) kv[u] = Kb[(tj8 + u) * 129 + qo + d];
            #pragma unroll
            for (int r = 0; r < 4; r++)
                #pragma unroll
                for (int u = 0; u < 8; u++)
                    acc[r][u] = fmaf(q[r], kv[u], acc[r][u]);
        }
        #pragma unroll
        for (int r = 0; r < 4; r++) {
            int i = ti + 16 * r;
            int ih = i >> wwsh, iw = i & (Ww - 1);
            #pragma unroll
            for (int u = 0; u < 8; u++) {
                int j = tj8 + u;
                int jh = j >> wwsh, jw = j & (Ww - 1);
                int rel = (ih - jh + Wh - 1) * (2 * Ww - 1) + (iw - jw + Ww - 1);
                Ss[(h * 64 + i) * 65 + j] = acc[r][u] * 0.125f + table[rel * 2 + h];
            }
        }
    }
    __syncthreads();

    // softmax per (h,i) row
    if (tid < 128) {
        float* row = Ss + tid * 65;
        float mx = -1e30f;
        #pragma unroll 8
        for (int j = 0; j < 64; j++) mx = fmaxf(mx, row[j]);
        float s = 0.f;
        #pragma unroll 8
        for (int j = 0; j < 64; j++) { float e = expf(row[j] - mx); row[j] = e; s += e; }
        float inv = 1.f / s;
        #pragma unroll 8
        for (int j = 0; j < 64; j++) row[j] *= inv;
    }
    __syncthreads();

    // O = S @ V  (into Qb)
    #pragma unroll
    for (int h = 0; h < 2; h++) {
        float acc[4][4] = {};
        #pragma unroll 4
        for (int j = 0; j < 64; j++) {
            float a[4], b[4];
            #pragma unroll
            for (int r = 0; r < 4; r++) a[r] = Ss[(h * 64 + tm + 16 * r) * 65 + j];
            #pragma unroll
            for (int u = 0; u < 4; u++) b[u] = Vb[j * 129 + h * 64 + tn4 + u];
            #pragma unroll
            for (int r = 0; r < 4; r++)
                #pragma unroll
                for (int u = 0; u < 4; u++)
                    acc[r][u] = fmaf(a[r], b[u], acc[r][u]);
        }
        #pragma unroll
        for (int r = 0; r < 4; r++)
            #pragma unroll
            for (int u = 0; u < 4; u++)
                Qb[(tm + 16 * r) * 129 + h * 64 + tn4 + u] = acc[r][u];
    }
    __syncthreads();

    // proj + bias + branch residual (xn) -> g_y
    for (int cc = 0; cc < 2; cc++) {
        __syncthreads();
        for (int e = tid; e < 128 * 64; e += 256) {
            int k = e >> 6, n = e & 63;
            Wst[e] = projw[k * 128 + cc * 64 + n];
        }
        __syncthreads();
        float acc[4][4] = {};
        #pragma unroll 4
        for (int k = 0; k < 128; k++) {
            float a[4], b[4];
            #pragma unroll
            for (int r = 0; r < 4; r++) a[r] = Qb[(tm + 16 * r) * 129 + k];
            #pragma unroll
            for (int u = 0; u < 4; u++) b[u] = Wst[k * 64 + tn4 + u];
            #pragma unroll
            for (int r = 0; r < 4; r++)
                #pragma unroll
                for (int u = 0; u < 4; u++)
                    acc[r][u] = fmaf(a[r], b[u], acc[r][u]);
        }
        #pragma unroll
        for (int r = 0; r < 4; r++) {
            int m = tm + 16 * r;
            int p = tokp[m];
            #pragma unroll
            for (int u = 0; u < 4; u++) {
                int col = cc * 64 + tn4 + u;
                g_y[(size_t)p * 256 + coff + col] =
                    acc[r][u] + projb[col] + Xs[m * 129 + col];
            }
        }
    }
}

// -------------------------------------------------- residual + LN2 stats
__global__ void __launch_bounds__(256) resid_ln2_kernel(const float* __restrict__ x) {
    extern __shared__ float sm[];      // [64][257]
    const int tid = threadIdx.x;
    const int pbase = blockIdx.x * 64;
    for (int e = tid; e < 64 * 256; e += 256) {
        int p = e >> 8, c = e & 255;
        sm[p * 257 + c] = g_y[(size_t)(pbase + p) * 256 + c];
    }
    __syncthreads();
    for (int e = tid; e < 64 * 256; e += 256) {
        int c = e >> 6, p = e & 63;
        sm[p * 257 + c] += x[c * HW + pbase + p];
    }
    __syncthreads();
    if (tid < 64) {
        float s = 0.f, sq = 0.f;
        #pragma unroll 8
        for (int c = 0; c < 256; c++) {
            float v = sm[tid * 257 + c];
            s += v; sq += v * v;
        }
        float m = s * (1.f / 256.f);
        float var = sq * (1.f / 256.f) - m * m;
        g_mean[pbase + tid] = m;
        g_rstd[pbase + tid] = rsqrtf(var + 1e-5f);
    }
    for (int e = tid; e < 64 * 256; e += 256) {
        int p = e >> 8, c = e & 255;
        g_y[(size_t)(pbase + p) * 256 + c] = sm[p * 257 + c];
    }
}

// -------------------------------------------------- MLP GEMM1 (LN2 in, GELU out)
__global__ void __launch_bounds__(256) mlp1_kernel(
    const float* __restrict__ w1, const float* __restrict__ b1,
    const float* __restrict__ g2, const float* __restrict__ bt2) {
    __shared__ __align__(16) float As[32 * 132];
    __shared__ __align__(16) float Bs[32 * 128];
    __shared__ float Ms[128], Rs[128];
    const int tid = threadIdx.x;
    const int m0 = blockIdx.y * 128;
    const int n0 = blockIdx.x * 128;
    const int tm8 = (tid & 15) * 8;
    const int tn8 = (tid >> 4) * 8;
    if (tid < 128) { Ms[tid] = g_mean[m0 + tid]; Rs[tid] = g_rstd[m0 + tid]; }
    float acc[8][8] = {};
    for (int k0 = 0; k0 < 256; k0 += 32) {
        __syncthreads();
        for (int e = tid; e < 128 * 32; e += 256) {
            int m = e >> 5, k = e & 31;
            float v = g_y[(size_t)(m0 + m) * 256 + k0 + k];
            As[k * 132 + m] = (v - Ms[m]) * Rs[m] * g2[k0 + k] + bt2[k0 + k];
        }
        for (int e = tid; e < 32 * 128; e += 256) {
            int k = e >> 7, n = e & 127;
            Bs[k * 128 + n] = w1[(size_t)(k0 + k) * 1024 + n0 + n];
        }
        __syncthreads();
        #pragma unroll 4
        for (int k = 0; k < 32; k++) {
            float4 a0 = *(const float4*)&As[k * 132 + tm8];
            float4 a1 = *(const float4*)&As[k * 132 + tm8 + 4];
            float4 b0 = *(const float4*)&Bs[k * 128 + tn8];
            float4 b1v = *(const float4*)&Bs[k * 128 + tn8 + 4];
            float av[8] = {a0.x, a0.y, a0.z, a0.w, a1.x, a1.y, a1.z, a1.w};
            float bv[8] = {b0.x, b0.y, b0.z, b0.w, b1v.x, b1v.y, b1v.z, b1v.w};
            #pragma unroll
            for (int v = 0; v < 8; v++)
                #pragma unroll
                for (int u = 0; u < 8; u++)
                    acc[v][u] = fmaf(av[v], bv[u], acc[v][u]);
        }
    }
    float bias[8];
    #pragma unroll
    for (int u = 0; u < 8; u++) bias[u] = b1[n0 + tn8 + u];
    #pragma unroll
    for (int v = 0; v < 8; v++) {
        size_t m = m0 + tm8 + v;
        float o[8];
        #pragma unroll
        for (int u = 0; u < 8; u++) {
            float t = acc[v][u] + bias[u];
            o[u] = 0.5f * t * (1.f + erff(t * 0.70710678118654752f));
        }
        float4* dst = (float4*)&g_h[m * 1024 + n0 + tn8];
        dst[0] = make_float4(o[0], o[1], o[2], o[3]);
        dst[1] = make_float4(o[4], o[5], o[6], o[7]);
    }
}

// -------------------------------------------------- MLP GEMM2 (+bias+residual, NCHW out)
__global__ void __launch_bounds__(256) mlp2_kernel(
    const float* __restrict__ w2, const float* __restrict__ b2,
    float* __restrict__ out) {
    __shared__ __align__(16) float As[32 * 132];
    __shared__ __align__(16) float Bs[32 * 128];
    const int tid = threadIdx.x;
    const int m0 = blockIdx.y * 128;
    const int n0 = blockIdx.x * 128;
    const int tm8 = (tid & 15) * 8;
    const int tn8 = (tid >> 4) * 8;
    float acc[8][8] = {};
    for (int k0 = 0; k0 < 1024; k0 += 32) {
        __syncthreads();
        for (int e = tid; e < 128 * 32; e += 256) {
            int m = e >> 5, k = e & 31;
            As[k * 132 + m] = g_h[(size_t)(m0 + m) * 1024 + k0 + k];
        }
        for (int e = tid; e < 32 * 128; e += 256) {
            int k = e >> 7, n = e & 127;
            Bs[k * 128 + n] = w2[(size_t)(k0 + k) * 256 + n0 + n];
        }
        __syncthreads();
        #pragma unroll 4
        for (int k = 0; k < 32; k++) {
            float4 a0 = *(const float4*)&As[k * 132 + tm8];
            float4 a1 = *(const float4*)&As[k * 132 + tm8 + 4];
            float4 b0 = *(const float4*)&Bs[k * 128 + tn8];
            float4 b1v = *(const float4*)&Bs[k * 128 + tn8 + 4];
            float av[8] = {a0.x, a0.y, a0.z, a0.w, a1.x, a1.y, a1.z, a1.w};
            float bv[8] = {b0.x, b0.y, b0.z, b0.w, b1v.x, b1v.y, b1v.z, b1v.w};
            #pragma unroll
            for (int v = 0; v < 8; v++)
                #pragma unroll
                for (int u = 0; u < 8; u++)
                    acc[v][u] = fmaf(av[v], bv[u], acc[v][u]);
        }
    }
    float bias[8];
    #pragma unroll
    for (int u = 0; u < 8; u++) bias[u] = b2[n0 + tn8 + u];
    #pragma unroll
    for (int v = 0; v < 8; v++) {
        size_t m = m0 + tm8 + v;
        float4 r0 = *(const float4*)&g_y[m * 256 + n0 + tn8];
        float4 r1 = *(const float4*)&g_y[m * 256 + n0 + tn8 + 4];
        float rv[8] = {r0.x, r0.y, r0.z, r0.w, r1.x, r1.y, r1.z, r1.w};
        #pragma unroll
        for (int u = 0; u < 8; u++) acc[v][u] += bias[u] + rv[u];
    }
    #pragma unroll
    for (int u = 0; u < 8; u++) {
        size_t n = n0 + tn8 + u;
        float4* dst = (float4*)&out[n * HW + m0 + tm8];
        dst[0] = make_float4(acc[0][u], acc[1][u], acc[2][u], acc[3][u]);
        dst[1] = make_float4(acc[4][u], acc[5][u], acc[6][u], acc[7][u]);
    }
}

extern "C" void kernel_launch(void* const* d_in, const int* in_sizes, int n_in,
                              void* d_out, int out_size) {
    const float* x       = (const float*)d_in[0];
    const float* norm1_g = (const float*)d_in[1];
    const float* norm1_b = (const float*)d_in[2];
    const float* qkv_r   = (const float*)d_in[3];
    const float* proj_rw = (const float*)d_in[4];
    const float* proj_rb = (const float*)d_in[5];
    const float* table_r = (const float*)d_in[6];
    const float* qkv_a   = (const float*)d_in[7];
    const float* proj_aw = (const float*)d_in[8];
    const float* proj_ab = (const float*)d_in[9];
    const float* table_a = (const float*)d_in[10];
    const float* norm2_g = (const float*)d_in[11];
    const float* norm2_b = (const float*)d_in[12];
    const float* mlp_w1  = (const float*)d_in[13];
    const float* mlp_b1  = (const float*)d_in[14];
    const float* mlp_w2  = (const float*)d_in[15];
    const float* mlp_b2  = (const float*)d_in[16];
    float* out = (float*)d_out;

    cudaFuncSetAttribute(ln1_kernel, cudaFuncAttributeMaxDynamicSharedMemorySize, LN1_SMEM);
    cudaFuncSetAttribute(attn_kernel, cudaFuncAttributeMaxDynamicSharedMemorySize, ATTN_SMEM);
    cudaFuncSetAttribute(resid_ln2_kernel, cudaFuncAttributeMaxDynamicSharedMemorySize, RES_SMEM);

    ln1_kernel<<<1024, 256, LN1_SMEM>>>(x, norm1_g, norm1_b);
    attn_kernel<<<dim3(1024, 2), 256, ATTN_SMEM>>>(qkv_r, proj_rw, proj_rb, table_r,
                                                   qkv_a, proj_aw, proj_ab, table_a);
    resid_ln2_kernel<<<1024, 256, RES_SMEM>>>(x);
    mlp1_kernel<<<dim3(8, 512), 256>>>(mlp_w1, mlp_b1, norm2_g, norm2_b);
    mlp2_kernel<<<dim3(2, 512), 256>>>(mlp_w2, mlp_b2, out);
}

// round 5
// speedup vs baseline: 1.2529x; 1.2529x over previous
#include <cuda_runtime.h>
#include <math.h>

#define HW 65536
#define WIDTH 256

__device__ float g_xn[(size_t)HW * 256];
__device__ float g_y[(size_t)HW * 256];
__device__ float g_h[(size_t)HW * 1024];
__device__ float g_mean[HW];
__device__ float g_rstd[HW];

#define LN1_SMEM ((256 * 65 + 128) * 4)
// Xs 64*129 + Qb 64*129 + Kb 64*129 + Vb 64*130 + Ss 128*65 + Wst 128*64 floats + 64 ints
#define ATTN_SMEM ((3 * 64 * 129 + 64 * 130 + 128 * 65 + 128 * 64) * 4 + 64 * 4)
#define RES_SMEM (64 * 257 * 4)

typedef unsigned long long u64t;

// ---- packed f32x2 helpers (Blackwell FFMA2 path) ----
__device__ __forceinline__ u64t pk2(float x) {
    u64t r; unsigned int u = __float_as_uint(x);
    asm("mov.b64 %0, {%1, %1};" : "=l"(r) : "r"(u));
    return r;
}
__device__ __forceinline__ void ffma2(u64t& d, u64t a, u64t b) {
    asm("fma.rn.f32x2 %0, %1, %2, %3;" : "=l"(d) : "l"(a), "l"(b), "l"(d));
}
__device__ __forceinline__ float2 upk(u64t v) {
    unsigned int lo, hi;
    asm("mov.b64 {%0, %1}, %2;" : "=r"(lo), "=r"(hi) : "l"(v));
    return make_float2(__uint_as_float(lo), __uint_as_float(hi));
}

// -------------------------------------------------------------- LN1
__global__ void __launch_bounds__(256) ln1_kernel(
    const float* __restrict__ x, const float* __restrict__ g1,
    const float* __restrict__ b1) {
    extern __shared__ float sm[];
    float* smean = sm + 256 * 65;
    float* srstd = smean + 64;
    const int tid = threadIdx.x;
    const int pbase = blockIdx.x * 64;
    for (int e = tid; e < 256 * 64; e += 256) {
        int c = e >> 6, p = e & 63;
        sm[c * 65 + p] = x[c * HW + pbase + p];
    }
    __syncthreads();
    if (tid < 64) {
        float s = 0.f, sq = 0.f;
        #pragma unroll 8
        for (int c = 0; c < 256; c++) {
            float v = sm[c * 65 + tid];
            s += v; sq += v * v;
        }
        float m = s * (1.f / 256.f);
        float var = sq * (1.f / 256.f) - m * m;
        smean[tid] = m;
        srstd[tid] = rsqrtf(var + 1e-5f);
    }
    __syncthreads();
    const float gc = g1[tid], bc = b1[tid];
    #pragma unroll 8
    for (int i = 0; i < 64; i++) {
        float v = sm[tid * 65 + i];
        g_xn[(size_t)(pbase + i) * 256 + tid] = (v - smean[i]) * srstd[i] * gc + bc;
    }
}

// -------------------------------------------------------------- Attention
__global__ void __launch_bounds__(256) attn_kernel(
    const float* __restrict__ qkv_r, const float* __restrict__ proj_r,
    const float* __restrict__ pb_r, const float* __restrict__ tab_r,
    const float* __restrict__ qkv_a, const float* __restrict__ proj_a,
    const float* __restrict__ pb_a, const float* __restrict__ tab_a) {
    extern __shared__ float sm[];
    float* Xs = sm;                    // 64 x 129
    float* Qb = Xs + 64 * 129;         // 64 x 129 (reused as O)
    float* Kb = Qb + 64 * 129;         // 64 x 129
    float* Vb = Kb + 64 * 129;         // 64 x 130 (even stride for 64-bit loads)
    float* Ss = Vb + 64 * 130;         // 128 x 65
    float* Wst = Ss + 128 * 65;        // 128 x 64
    int* tokp = (int*)(Wst + 128 * 64);

    const int tid = threadIdx.x;
    const int br = blockIdx.y;
    const float* qkvw = br ? qkv_a : qkv_r;
    const float* projw = br ? proj_a : proj_r;
    const float* projb = br ? pb_a : pb_r;
    const float* table = br ? tab_a : tab_r;
    const int coff = br ? 128 : 0;
    const int wwsh = br ? 4 : 2;
    const int Ww = 1 << wwsh;
    const int Wh = 64 >> wwsh;
    const int nWx = WIDTH >> wwsh;
    const int win = blockIdx.x;
    const int wy = win / nWx;
    const int wx = win - wy * nWx;
    const int row0 = wy * Wh, col0 = wx * Ww;

    if (tid < 64) {
        int ih = tid >> wwsh, iw = tid & (Ww - 1);
        tokp[tid] = (row0 + ih) * WIDTH + col0 + iw;
    }
    __syncthreads();
    for (int e = tid; e < 64 * 128; e += 256) {
        int t = e >> 7, c = e & 127;
        Xs[t * 129 + c] = g_xn[(size_t)tokp[t] * 256 + coff + c];
    }

    const int tm = tid & 15;
    const int tn4 = (tid >> 4) * 4;
    const u64t* W64 = (const u64t*)Wst;

    // QKV: 6 chunks of 64 output cols (Q0,Q1,K0,K1,V0,V1), f32x2 packed on n
    for (int cc = 0; cc < 6; cc++) {
        __syncthreads();
        for (int e = tid; e < 128 * 64; e += 256) {
            int k = e >> 6, n = e & 63;
            Wst[e] = qkvw[k * 384 + cc * 64 + n];
        }
        __syncthreads();
        u64t acc2[4][2] = {};
        #pragma unroll 4
        for (int k = 0; k < 128; k++) {
            u64t pa[4], b2[2];
            #pragma unroll
            for (int r = 0; r < 4; r++) pa[r] = pk2(Xs[(tm + 16 * r) * 129 + k]);
            #pragma unroll
            for (int u = 0; u < 2; u++) b2[u] = W64[k * 32 + (tn4 >> 1) + u];
            #pragma unroll
            for (int r = 0; r < 4; r++)
                #pragma unroll
                for (int u = 0; u < 2; u++)
                    ffma2(acc2[r][u], pa[r], b2[u]);
        }
        float* dst = (cc < 2) ? Qb : ((cc < 4) ? Kb : Vb);
        const int ds = (cc < 4) ? 129 : 130;
        const int cb = (cc & 1) * 64;
        #pragma unroll
        for (int r = 0; r < 4; r++)
            #pragma unroll
            for (int u = 0; u < 2; u++) {
                float2 p = upk(acc2[r][u]);
                dst[(tm + 16 * r) * ds + cb + tn4 + 2 * u] = p.x;
                dst[(tm + 16 * r) * ds + cb + tn4 + 2 * u + 1] = p.y;
            }
    }
    __syncthreads();

    // scores + rel-pos bias (scalar: K rows not n-contiguous)
    {
        const int h = tid >> 7;
        const int rest = tid & 127;
        const int ti = rest & 15;
        const int tj8 = (rest >> 4) * 8;
        const int qo = h * 64;
        float acc[4][8] = {};
        #pragma unroll 4
        for (int d = 0; d < 64; d++) {
            float q[4], kv[8];
            #pragma unroll
            for (int r = 0; r < 4; r++) q[r] = Qb[(ti + 16 * r) * 129 + qo + d];
            #pragma unroll
            for (int u = 0; u < 8; u++) kv[u] = Kb[(tj8 + u) * 129 + qo + d];
            #pragma unroll
            for (int r = 0; r < 4; r++)
                #pragma unroll
                for (int u = 0; u < 8; u++)
                    acc[r][u] = fmaf(q[r], kv[u], acc[r][u]);
        }
        #pragma unroll
        for (int r = 0; r < 4; r++) {
            int i = ti + 16 * r;
            int ih = i >> wwsh, iw = i & (Ww - 1);
            #pragma unroll
            for (int u = 0; u < 8; u++) {
                int j = tj8 + u;
                int jh = j >> wwsh, jw = j & (Ww - 1);
                int rel = (ih - jh + Wh - 1) * (2 * Ww - 1) + (iw - jw + Ww - 1);
                Ss[(h * 64 + i) * 65 + j] = acc[r][u] * 0.125f + table[rel * 2 + h];
            }
        }
    }
    __syncthreads();

    // softmax per (h,i) row
    if (tid < 128) {
        float* row = Ss + tid * 65;
        float mx = -1e30f;
        #pragma unroll 8
        for (int j = 0; j < 64; j++) mx = fmaxf(mx, row[j]);
        float s = 0.f;
        #pragma unroll 8
        for (int j = 0; j < 64; j++) { float e = expf(row[j] - mx); row[j] = e; s += e; }
        float inv = 1.f / s;
        #pragma unroll 8
        for (int j = 0; j < 64; j++) row[j] *= inv;
    }
    __syncthreads();

    // O = S @ V  (into Qb), f32x2 packed on n
    {
        const u64t* V64 = (const u64t*)Vb;
        #pragma unroll
        for (int h = 0; h < 2; h++) {
            u64t acc2[4][2] = {};
            const int vcol = (h * 64 + tn4) >> 1;
            #pragma unroll 4
            for (int j = 0; j < 64; j++) {
                u64t pa[4], b2[2];
                #pragma unroll
                for (int r = 0; r < 4; r++)
                    pa[r] = pk2(Ss[(h * 64 + tm + 16 * r) * 65 + j]);
                #pragma unroll
                for (int u = 0; u < 2; u++) b2[u] = V64[j * 65 + vcol + u];
                #pragma unroll
                for (int r = 0; r < 4; r++)
                    #pragma unroll
                    for (int u = 0; u < 2; u++)
                        ffma2(acc2[r][u], pa[r], b2[u]);
            }
            #pragma unroll
            for (int r = 0; r < 4; r++)
                #pragma unroll
                for (int u = 0; u < 2; u++) {
                    float2 p = upk(acc2[r][u]);
                    Qb[(tm + 16 * r) * 129 + h * 64 + tn4 + 2 * u] = p.x;
                    Qb[(tm + 16 * r) * 129 + h * 64 + tn4 + 2 * u + 1] = p.y;
                }
        }
    }
    __syncthreads();

    // proj + bias + branch residual (xn) -> g_y, f32x2 packed on n
    for (int cc = 0; cc < 2; cc++) {
        __syncthreads();
        for (int e = tid; e < 128 * 64; e += 256) {
            int k = e >> 6, n = e & 63;
            Wst[e] = projw[k * 128 + cc * 64 + n];
        }
        __syncthreads();
        u64t acc2[4][2] = {};
        #pragma unroll 4
        for (int k = 0; k < 128; k++) {
            u64t pa[4], b2[2];
            #pragma unroll
            for (int r = 0; r < 4; r++) pa[r] = pk2(Qb[(tm + 16 * r) * 129 + k]);
            #pragma unroll
            for (int u = 0; u < 2; u++) b2[u] = W64[k * 32 + (tn4 >> 1) + u];
            #pragma unroll
            for (int r = 0; r < 4; r++)
                #pragma unroll
                for (int u = 0; u < 2; u++)
                    ffma2(acc2[r][u], pa[r], b2[u]);
        }
        #pragma unroll
        for (int r = 0; r < 4; r++) {
            int m = tm + 16 * r;
            int p = tokp[m];
            #pragma unroll
            for (int u = 0; u < 2; u++) {
                float2 pv = upk(acc2[r][u]);
                int c0 = cc * 64 + tn4 + 2 * u;
                g_y[(size_t)p * 256 + coff + c0] =
                    pv.x + projb[c0] + Xs[m * 129 + c0];
                g_y[(size_t)p * 256 + coff + c0 + 1] =
                    pv.y + projb[c0 + 1] + Xs[m * 129 + c0 + 1];
            }
        }
    }
}

// -------------------------------------------------- residual + LN2 stats
__global__ void __launch_bounds__(256) resid_ln2_kernel(const float* __restrict__ x) {
    extern __shared__ float sm[];      // [64][257]
    const int tid = threadIdx.x;
    const int pbase = blockIdx.x * 64;
    for (int e = tid; e < 64 * 256; e += 256) {
        int p = e >> 8, c = e & 255;
        sm[p * 257 + c] = g_y[(size_t)(pbase + p) * 256 + c];
    }
    __syncthreads();
    for (int e = tid; e < 64 * 256; e += 256) {
        int c = e >> 6, p = e & 63;
        sm[p * 257 + c] += x[c * HW + pbase + p];
    }
    __syncthreads();
    if (tid < 64) {
        float s = 0.f, sq = 0.f;
        #pragma unroll 8
        for (int c = 0; c < 256; c++) {
            float v = sm[tid * 257 + c];
            s += v; sq += v * v;
        }
        float m = s * (1.f / 256.f);
        float var = sq * (1.f / 256.f) - m * m;
        g_mean[pbase + tid] = m;
        g_rstd[pbase + tid] = rsqrtf(var + 1e-5f);
    }
    for (int e = tid; e < 64 * 256; e += 256) {
        int p = e >> 8, c = e & 255;
        g_y[(size_t)(pbase + p) * 256 + c] = sm[p * 257 + c];
    }
}

// -------------------------------------------------- MLP GEMM1 (LN2 in, GELU out)
__global__ void __launch_bounds__(256) mlp1_kernel(
    const float* __restrict__ w1, const float* __restrict__ b1,
    const float* __restrict__ g2, const float* __restrict__ bt2) {
    __shared__ __align__(16) float As[32 * 132];
    __shared__ __align__(16) float Bs[32 * 128];
    __shared__ float Ms[128], Rs[128];
    const int tid = threadIdx.x;
    const int m0 = blockIdx.y * 128;
    const int n0 = blockIdx.x * 128;
    const int tm8 = (tid & 15) * 8;
    const int tn8 = (tid >> 4) * 8;
    const u64t* B64 = (const u64t*)Bs;
    if (tid < 128) { Ms[tid] = g_mean[m0 + tid]; Rs[tid] = g_rstd[m0 + tid]; }
    u64t acc2[8][4] = {};
    for (int k0 = 0; k0 < 256; k0 += 32) {
        __syncthreads();
        for (int e = tid; e < 128 * 32; e += 256) {
            int m = e >> 5, k = e & 31;
            float v = g_y[(size_t)(m0 + m) * 256 + k0 + k];
            As[k * 132 + m] = (v - Ms[m]) * Rs[m] * g2[k0 + k] + bt2[k0 + k];
        }
        for (int e = tid; e < 32 * 128; e += 256) {
            int k = e >> 7, n = e & 127;
            Bs[k * 128 + n] = w1[(size_t)(k0 + k) * 1024 + n0 + n];
        }
        __syncthreads();
        #pragma unroll 4
        for (int k = 0; k < 32; k++) {
            float4 a0 = *(const float4*)&As[k * 132 + tm8];
            float4 a1 = *(const float4*)&As[k * 132 + tm8 + 4];
            u64t pa[8] = {pk2(a0.x), pk2(a0.y), pk2(a0.z), pk2(a0.w),
                          pk2(a1.x), pk2(a1.y), pk2(a1.z), pk2(a1.w)};
            u64t b2[4];
            #pragma unroll
            for (int u = 0; u < 4; u++) b2[u] = B64[k * 64 + (tn8 >> 1) + u];
            #pragma unroll
            for (int v = 0; v < 8; v++)
                #pragma unroll
                for (int u = 0; u < 4; u++)
                    ffma2(acc2[v][u], pa[v], b2[u]);
        }
    }
    float bias[8];
    #pragma unroll
    for (int u = 0; u < 8; u++) bias[u] = b1[n0 + tn8 + u];
    #pragma unroll
    for (int v = 0; v < 8; v++) {
        size_t m = m0 + tm8 + v;
        float o[8];
        #pragma unroll
        for (int u = 0; u < 4; u++) {
            float2 p = upk(acc2[v][u]);
            float t0 = p.x + bias[2 * u];
            float t1 = p.y + bias[2 * u + 1];
            o[2 * u]     = 0.5f * t0 * (1.f + erff(t0 * 0.70710678118654752f));
            o[2 * u + 1] = 0.5f * t1 * (1.f + erff(t1 * 0.70710678118654752f));
        }
        float4* dst = (float4*)&g_h[m * 1024 + n0 + tn8];
        dst[0] = make_float4(o[0], o[1], o[2], o[3]);
        dst[1] = make_float4(o[4], o[5], o[6], o[7]);
    }
}

// -------------------------------------------------- MLP GEMM2 (+bias+residual, NCHW out)
__global__ void __launch_bounds__(256) mlp2_kernel(
    const float* __restrict__ w2, const float* __restrict__ b2,
    float* __restrict__ out) {
    __shared__ __align__(16) float As[32 * 132];
    __shared__ __align__(16) float Bs[32 * 128];
    const int tid = threadIdx.x;
    const int m0 = blockIdx.y * 128;
    const int n0 = blockIdx.x * 128;
    const int tm8 = (tid & 15) * 8;
    const int tn8 = (tid >> 4) * 8;
    const u64t* B64 = (const u64t*)Bs;
    u64t acc2[8][4] = {};
    for (int k0 = 0; k0 < 1024; k0 += 32) {
        __syncthreads();
        for (int e = tid; e < 128 * 32; e += 256) {
            int m = e >> 5, k = e & 31;
            As[k * 132 + m] = g_h[(size_t)(m0 + m) * 1024 + k0 + k];
        }
        for (int e = tid; e < 32 * 128; e += 256) {
            int k = e >> 7, n = e & 127;
            Bs[k * 128 + n] = w2[(size_t)(k0 + k) * 256 + n0 + n];
        }
        __syncthreads();
        #pragma unroll 4
        for (int k = 0; k < 32; k++) {
            float4 a0 = *(const float4*)&As[k * 132 + tm8];
            float4 a1 = *(const float4*)&As[k * 132 + tm8 + 4];
            u64t pa[8] = {pk2(a0.x), pk2(a0.y), pk2(a0.z), pk2(a0.w),
                          pk2(a1.x), pk2(a1.y), pk2(a1.z), pk2(a1.w)};
            u64t b2[4];
            #pragma unroll
            for (int u = 0; u < 4; u++) b2[u] = B64[k * 64 + (tn8 >> 1) + u];
            #pragma unroll
            for (int v = 0; v < 8; v++)
                #pragma unroll
                for (int u = 0; u < 4; u++)
                    ffma2(acc2[v][u], pa[v], b2[u]);
        }
    }
    float bias[8];
    #pragma unroll
    for (int u = 0; u < 8; u++) bias[u] = b2[n0 + tn8 + u];
    float oc[8][8];
    #pragma unroll
    for (int v = 0; v < 8; v++) {
        size_t m = m0 + tm8 + v;
        #pragma unroll
        for (int u = 0; u < 4; u++) {
            float2 p = upk(acc2[v][u]);
            oc[v][2 * u]     = p.x + bias[2 * u]     + g_y[m * 256 + n0 + tn8 + 2 * u];
            oc[v][2 * u + 1] = p.y + bias[2 * u + 1] + g_y[m * 256 + n0 + tn8 + 2 * u + 1];
        }
    }
    #pragma unroll
    for (int u = 0; u < 8; u++) {
        size_t n = n0 + tn8 + u;
        float4* dst = (float4*)&out[n * HW + m0 + tm8];
        dst[0] = make_float4(oc[0][u], oc[1][u], oc[2][u], oc[3][u]);
        dst[1] = make_float4(oc[4][u], oc[5][u], oc[6][u], oc[7][u]);
    }
}

extern "C" void kernel_launch(void* const* d_in, const int* in_sizes, int n_in,
                              void* d_out, int out_size) {
    const float* x       = (const float*)d_in[0];
    const float* norm1_g = (const float*)d_in[1];
    const float* norm1_b = (const float*)d_in[2];
    const float* qkv_r   = (const float*)d_in[3];
    const float* proj_rw = (const float*)d_in[4];
    const float* proj_rb = (const float*)d_in[5];
    const float* table_r = (const float*)d_in[6];
    const float* qkv_a   = (const float*)d_in[7];
    const float* proj_aw = (const float*)d_in[8];
    const float* proj_ab = (const float*)d_in[9];
    const float* table_a = (const float*)d_in[10];
    const float* norm2_g = (const float*)d_in[11];
    const float* norm2_b = (const float*)d_in[12];
    const float* mlp_w1  = (const float*)d_in[13];
    const float* mlp_b1  = (const float*)d_in[14];
    const float* mlp_w2  = (const float*)d_in[15];
    const float* mlp_b2  = (const float*)d_in[16];
    float* out = (float*)d_out;

    cudaFuncSetAttribute(ln1_kernel, cudaFuncAttributeMaxDynamicSharedMemorySize, LN1_SMEM);
    cudaFuncSetAttribute(attn_kernel, cudaFuncAttributeMaxDynamicSharedMemorySize, ATTN_SMEM);
    cudaFuncSetAttribute(resid_ln2_kernel, cudaFuncAttributeMaxDynamicSharedMemorySize, RES_SMEM);

    ln1_kernel<<<1024, 256, LN1_SMEM>>>(x, norm1_g, norm1_b);
    attn_kernel<<<dim3(1024, 2), 256, ATTN_SMEM>>>(qkv_r, proj_rw, proj_rb, table_r,
                                                   qkv_a, proj_aw, proj_ab, table_a);
    resid_ln2_kernel<<<1024, 256, RES_SMEM>>>(x);
    mlp1_kernel<<<dim3(8, 512), 256>>>(mlp_w1, mlp_b1, norm2_g, norm2_b);
    mlp2_kernel<<<dim3(2, 512), 256>>>(mlp_w2, mlp_b2, out);
}

// round 13
// speedup vs baseline: 2.2787x; 1.8187x over previous
#include <cuda_runtime.h>
#include <math.h>
#include <stdint.h>

#define HW 65536
#define WIDTH 256

__device__ float g_xn[(size_t)HW * 256];
__device__ float g_y[(size_t)HW * 256];
__device__ float g_h[(size_t)HW * 1024];
__device__ float g_mean[HW];
__device__ float g_rstd[HW];

#define LN1_SMEM ((256 * 65 + 128) * 4)
#define ATTN_SMEM ((3 * 64 * 129 + 64 * 130 + 128 * 65 + 128 * 64) * 4 + 64 * 4)
#define RES_SMEM (64 * 257 * 4)

typedef unsigned long long u64t;

// ---- packed f32x2 helpers ----
__device__ __forceinline__ u64t pk2(float x) {
    u64t r; unsigned int u = __float_as_uint(x);
    asm("mov.b64 %0, {%1, %1};" : "=l"(r) : "r"(u));
    return r;
}
__device__ __forceinline__ void ffma2(u64t& d, u64t a, u64t b) {
    asm("fma.rn.f32x2 %0, %1, %2, %3;" : "=l"(d) : "l"(a), "l"(b), "l"(d));
}
__device__ __forceinline__ float2 upk(u64t v) {
    unsigned int lo, hi;
    asm("mov.b64 {%0, %1}, %2;" : "=r"(lo), "=r"(hi) : "l"(v));
    return make_float2(__uint_as_float(lo), __uint_as_float(hi));
}

// ---- tf32 mma.sync helpers (standard PTX, works on plain sm_103 target) ----
__device__ __forceinline__ float to_tf32(float x) {
    float r; asm("cvt.rna.tf32.f32 %0, %1;" : "=f"(r) : "f"(x)); return r;
}
__device__ __forceinline__ void mma1688(float* d, const uint32_t* a, const uint32_t* b) {
    asm volatile(
        "mma.sync.aligned.m16n8k8.row.col.f32.tf32.tf32.f32 "
        "{%0,%1,%2,%3}, {%4,%5,%6,%7}, {%8,%9}, {%0,%1,%2,%3};"
        : "+f"(d[0]), "+f"(d[1]), "+f"(d[2]), "+f"(d[3])
        : "r"(a[0]), "r"(a[1]), "r"(a[2]), "r"(a[3]), "r"(b[0]), "r"(b[1]));
}

// MMA kernel smem layout (float offsets)
#define SBUF 8832
#define EXTOF 17664
#define MMA_SMEM ((17664 + 896) * 4)

__device__ __forceinline__ void mma_chunk(const float* As, const float* Bs,
                                          int wm, int wn, int gid, int tig,
                                          float acc[2][8][4]) {
    #pragma unroll
    for (int ks = 0; ks < 4; ks++) {
        const int k0 = ks * 8;
        uint32_t a[2][4], b[8][2];
        #pragma unroll
        for (int mt = 0; mt < 2; mt++) {
            int r0 = wm * 32 + mt * 16 + gid;
            a[mt][0] = __float_as_uint(As[r0 * 36 + k0 + tig]);
            a[mt][1] = __float_as_uint(As[(r0 + 8) * 36 + k0 + tig]);
            a[mt][2] = __float_as_uint(As[r0 * 36 + k0 + tig + 4]);
            a[mt][3] = __float_as_uint(As[(r0 + 8) * 36 + k0 + tig + 4]);
        }
        #pragma unroll
        for (int nt = 0; nt < 8; nt++) {
            int n = wn * 64 + nt * 8 + gid;
            b[nt][0] = __float_as_uint(Bs[(k0 + tig) * 132 + n]);
            b[nt][1] = __float_as_uint(Bs[(k0 + tig + 4) * 132 + n]);
        }
        #pragma unroll
        for (int mt = 0; mt < 2; mt++)
            #pragma unroll
            for (int nt = 0; nt < 8; nt++)
                mma1688(acc[mt][nt], a[mt], b[nt]);
    }
}

// -------------------------------------------------------------- LN1
__global__ void __launch_bounds__(256) ln1_kernel(
    const float* __restrict__ x, const float* __restrict__ g1,
    const float* __restrict__ b1) {
    extern __shared__ float sm[];
    float* smean = sm + 256 * 65;
    float* srstd = smean + 64;
    const int tid = threadIdx.x;
    const int pbase = blockIdx.x * 64;
    for (int e = tid; e < 256 * 64; e += 256) {
        int c = e >> 6, p = e & 63;
        sm[c * 65 + p] = x[c * HW + pbase + p];
    }
    __syncthreads();
    if (tid < 64) {
        float s = 0.f, sq = 0.f;
        #pragma unroll 8
        for (int c = 0; c < 256; c++) {
            float v = sm[c * 65 + tid];
            s += v; sq += v * v;
        }
        float m = s * (1.f / 256.f);
        float var = sq * (1.f / 256.f) - m * m;
        smean[tid] = m;
        srstd[tid] = rsqrtf(var + 1e-5f);
    }
    __syncthreads();
    const float gc = g1[tid], bc = b1[tid];
    #pragma unroll 8
    for (int i = 0; i < 64; i++) {
        float v = sm[tid * 65 + i];
        g_xn[(size_t)(pbase + i) * 256 + tid] = (v - smean[i]) * srstd[i] * gc + bc;
    }
}

// -------------------------------------------------------------- Attention (FFMA2)
__global__ void __launch_bounds__(256) attn_kernel(
    const float* __restrict__ qkv_r, const float* __restrict__ proj_r,
    const float* __restrict__ pb_r, const float* __restrict__ tab_r,
    const float* __restrict__ qkv_a, const float* __restrict__ proj_a,
    const float* __restrict__ pb_a, const float* __restrict__ tab_a) {
    extern __shared__ float sm[];
    float* Xs = sm;
    float* Qb = Xs + 64 * 129;
    float* Kb = Qb + 64 * 129;
    float* Vb = Kb + 64 * 129;         // 64 x 130
    float* Ss = Vb + 64 * 130;         // 128 x 65
    float* Wst = Ss + 128 * 65;        // 128 x 64
    int* tokp = (int*)(Wst + 128 * 64);

    const int tid = threadIdx.x;
    const int br = blockIdx.y;
    const float* qkvw = br ? qkv_a : qkv_r;
    const float* projw = br ? proj_a : proj_r;
    const float* projb = br ? pb_a : pb_r;
    const float* table = br ? tab_a : tab_r;
    const int coff = br ? 128 : 0;
    const int wwsh = br ? 4 : 2;
    const int Ww = 1 << wwsh;
    const int Wh = 64 >> wwsh;
    const int nWx = WIDTH >> wwsh;
    const int win = blockIdx.x;
    const int wy = win / nWx;
    const int wx = win - wy * nWx;
    const int row0 = wy * Wh, col0 = wx * Ww;

    if (tid < 64) {
        int ih = tid >> wwsh, iw = tid & (Ww - 1);
        tokp[tid] = (row0 + ih) * WIDTH + col0 + iw;
    }
    __syncthreads();
    for (int e = tid; e < 64 * 128; e += 256) {
        int t = e >> 7, c = e & 127;
        Xs[t * 129 + c] = g_xn[(size_t)tokp[t] * 256 + coff + c];
    }

    const int tm = tid & 15;
    const int tn4 = (tid >> 4) * 4;
    const u64t* W64 = (const u64t*)Wst;

    for (int cc = 0; cc < 6; cc++) {
        __syncthreads();
        for (int e = tid; e < 128 * 64; e += 256) {
            int k = e >> 6, n = e & 63;
            Wst[e] = qkvw[k * 384 + cc * 64 + n];
        }
        __syncthreads();
        u64t acc2[4][2] = {};
        #pragma unroll 4
        for (int k = 0; k < 128; k++) {
            u64t pa[4], b2[2];
            #pragma unroll
            for (int r = 0; r < 4; r++) pa[r] = pk2(Xs[(tm + 16 * r) * 129 + k]);
            #pragma unroll
            for (int u = 0; u < 2; u++) b2[u] = W64[k * 32 + (tn4 >> 1) + u];
            #pragma unroll
            for (int r = 0; r < 4; r++)
                #pragma unroll
                for (int u = 0; u < 2; u++)
                    ffma2(acc2[r][u], pa[r], b2[u]);
        }
        float* dst = (cc < 2) ? Qb : ((cc < 4) ? Kb : Vb);
        const int ds = (cc < 4) ? 129 : 130;
        const int cb = (cc & 1) * 64;
        #pragma unroll
        for (int r = 0; r < 4; r++)
            #pragma unroll
            for (int u = 0; u < 2; u++) {
                float2 p = upk(acc2[r][u]);
                dst[(tm + 16 * r) * ds + cb + tn4 + 2 * u] = p.x;
                dst[(tm + 16 * r) * ds + cb + tn4 + 2 * u + 1] = p.y;
            }
    }
    __syncthreads();

    {
        const int h = tid >> 7;
        const int rest = tid & 127;
        const int ti = rest & 15;
        const int tj8 = (rest >> 4) * 8;
        const int qo = h * 64;
        float acc[4][8] = {};
        #pragma unroll 4
        for (int d = 0; d < 64; d++) {
            float q[4], kv[8];
            #pragma unroll
            for (int r = 0; r < 4; r++) q[r] = Qb[(ti + 16 * r) * 129 + qo + d];
            #pragma unroll
            for (int u = 0; u < 8; u++) kv[u] = Kb[(tj8 + u) * 129 + qo + d];
            #pragma unroll
            for (int r = 0; r < 4; r++)
                #pragma unroll
                for (int u = 0; u < 8; u++)
                    acc[r][u] = fmaf(q[r], kv[u], acc[r][u]);
        }
        #pragma unroll
        for (int r = 0; r < 4; r++) {
            int i = ti + 16 * r;
            int ih = i >> wwsh, iw = i & (Ww - 1);
            #pragma unroll
            for (int u = 0; u < 8; u++) {
                int j = tj8 + u;
                int jh = j >> wwsh, jw = j & (Ww - 1);
                int rel = (ih - jh + Wh - 1) * (2 * Ww - 1) + (iw - jw + Ww - 1);
                Ss[(h * 64 + i) * 65 + j] = acc[r][u] * 0.125f + table[rel * 2 + h];
            }
        }
    }
    __syncthreads();

    if (tid < 128) {
        float* row = Ss + tid * 65;
        float mx = -1e30f;
        #pragma unroll 8
        for (int j = 0; j < 64; j++) mx = fmaxf(mx, row[j]);
        float s = 0.f;
        #pragma unroll 8
        for (int j = 0; j < 64; j++) { float e = expf(row[j] - mx); row[j] = e; s += e; }
        float inv = 1.f / s;
        #pragma unroll 8
        for (int j = 0; j < 64; j++) row[j] *= inv;
    }
    __syncthreads();

    {
        const u64t* V64 = (const u64t*)Vb;
        #pragma unroll
        for (int h = 0; h < 2; h++) {
            u64t acc2[4][2] = {};
            const int vcol = (h * 64 + tn4) >> 1;
            #pragma unroll 4
            for (int j = 0; j < 64; j++) {
                u64t pa[4], b2[2];
                #pragma unroll
                for (int r = 0; r < 4; r++)
                    pa[r] = pk2(Ss[(h * 64 + tm + 16 * r) * 65 + j]);
                #pragma unroll
                for (int u = 0; u < 2; u++) b2[u] = V64[j * 65 + vcol + u];
                #pragma unroll
                for (int r = 0; r < 4; r++)
                    #pragma unroll
                    for (int u = 0; u < 2; u++)
                        ffma2(acc2[r][u], pa[r], b2[u]);
            }
            #pragma unroll
            for (int r = 0; r < 4; r++)
                #pragma unroll
                for (int u = 0; u < 2; u++) {
                    float2 p = upk(acc2[r][u]);
                    Qb[(tm + 16 * r) * 129 + h * 64 + tn4 + 2 * u] = p.x;
                    Qb[(tm + 16 * r) * 129 + h * 64 + tn4 + 2 * u + 1] = p.y;
                }
        }
    }
    __syncthreads();

    for (int cc = 0; cc < 2; cc++) {
        __syncthreads();
        for (int e = tid; e < 128 * 64; e += 256) {
            int k = e >> 6, n = e & 63;
            Wst[e] = projw[k * 128 + cc * 64 + n];
        }
        __syncthreads();
        u64t acc2[4][2] = {};
        #pragma unroll 4
        for (int k = 0; k < 128; k++) {
            u64t pa[4], b2[2];
            #pragma unroll
            for (int r = 0; r < 4; r++) pa[r] = pk2(Qb[(tm + 16 * r) * 129 + k]);
            #pragma unroll
            for (int u = 0; u < 2; u++) b2[u] = W64[k * 32 + (tn4 >> 1) + u];
            #pragma unroll
            for (int r = 0; r < 4; r++)
                #pragma unroll
                for (int u = 0; u < 2; u++)
                    ffma2(acc2[r][u], pa[r], b2[u]);
        }
        #pragma unroll
        for (int r = 0; r < 4; r++) {
            int m = tm + 16 * r;
            int p = tokp[m];
            #pragma unroll
            for (int u = 0; u < 2; u++) {
                float2 pv = upk(acc2[r][u]);
                int c0 = cc * 64 + tn4 + 2 * u;
                g_y[(size_t)p * 256 + coff + c0] =
                    pv.x + projb[c0] + Xs[m * 129 + c0];
                g_y[(size_t)p * 256 + coff + c0 + 1] =
                    pv.y + projb[c0 + 1] + Xs[m * 129 + c0 + 1];
            }
        }
    }
}

// -------------------------------------------------- residual + LN2 stats
__global__ void __launch_bounds__(256) resid_ln2_kernel(const float* __restrict__ x) {
    extern __shared__ float sm[];
    const int tid = threadIdx.x;
    const int pbase = blockIdx.x * 64;
    for (int e = tid; e < 64 * 256; e += 256) {
        int p = e >> 8, c = e & 255;
        sm[p * 257 + c] = g_y[(size_t)(pbase + p) * 256 + c];
    }
    __syncthreads();
    for (int e = tid; e < 64 * 256; e += 256) {
        int c = e >> 6, p = e & 63;
        sm[p * 257 + c] += x[c * HW + pbase + p];
    }
    __syncthreads();
    if (tid < 64) {
        float s = 0.f, sq = 0.f;
        #pragma unroll 8
        for (int c = 0; c < 256; c++) {
            float v = sm[tid * 257 + c];
            s += v; sq += v * v;
        }
        float m = s * (1.f / 256.f);
        float var = sq * (1.f / 256.f) - m * m;
        g_mean[pbase + tid] = m;
        g_rstd[pbase + tid] = rsqrtf(var + 1e-5f);
    }
    for (int e = tid; e < 64 * 256; e += 256) {
        int p = e >> 8, c = e & 255;
        g_y[(size_t)(pbase + p) * 256 + c] = sm[p * 257 + c];
    }
}

// -------------------------------------------------- MLP GEMM1 (tf32 mma.sync, LN in, GELU out)
__global__ void __launch_bounds__(256) mlp1_mma(
    const float* __restrict__ w1, const float* __restrict__ b1,
    const float* __restrict__ g2, const float* __restrict__ bt2) {
    extern __shared__ __align__(16) float smf[];
    float* biass = smf + EXTOF;
    float* Ms = biass + 128;
    float* Rs = Ms + 128;
    float* g2s = Rs + 128;
    float* bt2s = g2s + 256;
    const int tid = threadIdx.x;
    const int wid = tid >> 5, lane = tid & 31;
    const int gid = lane >> 2, tig = lane & 3;
    const int wm = wid & 3, wn = wid >> 2;
    const int m0 = blockIdx.y * 128, n0 = blockIdx.x * 128;

    if (tid < 128) {
        Ms[tid] = g_mean[m0 + tid];
        Rs[tid] = g_rstd[m0 + tid];
        biass[tid] = b1[n0 + tid];
    }
    g2s[tid] = g2[tid]; bt2s[tid] = bt2[tid];
    __syncthreads();

    float acc[2][8][4] = {};
    float4 ra[4], rb[4];

    #pragma unroll
    for (int i = 0; i < 4; i++) {
        int idx = i * 256 + tid;
        ra[i] = *(const float4*)&g_y[(size_t)(m0 + (idx >> 3)) * 256 + (idx & 7) * 4];
        rb[i] = *(const float4*)&w1[(size_t)(idx >> 5) * 1024 + n0 + (idx & 31) * 4];
    }
    {
        float* As = smf; float* Bs = smf + 4608;
        #pragma unroll
        for (int i = 0; i < 4; i++) {
            int idx = i * 256 + tid;
            int m = idx >> 3, kq = idx & 7, kg = kq * 4;
            float mn = Ms[m], rs = Rs[m];
            float4 v = ra[i];
            v.x = to_tf32((v.x - mn) * rs * g2s[kg] + bt2s[kg]);
            v.y = to_tf32((v.y - mn) * rs * g2s[kg + 1] + bt2s[kg + 1]);
            v.z = to_tf32((v.z - mn) * rs * g2s[kg + 2] + bt2s[kg + 2]);
            v.w = to_tf32((v.w - mn) * rs * g2s[kg + 3] + bt2s[kg + 3]);
            *(float4*)&As[m * 36 + kq * 4] = v;
            int kr = idx >> 5, nq = idx & 31;
            float4 w = rb[i];
            w.x = to_tf32(w.x); w.y = to_tf32(w.y); w.z = to_tf32(w.z); w.w = to_tf32(w.w);
            *(float4*)&Bs[kr * 132 + nq * 4] = w;
        }
    }
    __syncthreads();

    for (int c = 0; c < 8; c++) {
        if (c + 1 < 8) {
            #pragma unroll
            for (int i = 0; i < 4; i++) {
                int idx = i * 256 + tid;
                ra[i] = *(const float4*)&g_y[(size_t)(m0 + (idx >> 3)) * 256 + (c + 1) * 32 + (idx & 7) * 4];
                rb[i] = *(const float4*)&w1[(size_t)((c + 1) * 32 + (idx >> 5)) * 1024 + n0 + (idx & 31) * 4];
            }
        }
        {
            const float* As = smf + (c & 1) * SBUF;
            mma_chunk(As, As + 4608, wm, wn, gid, tig, acc);
        }
        if (c + 1 < 8) {
            float* As = smf + ((c + 1) & 1) * SBUF;
            float* Bs = As + 4608;
            #pragma unroll
            for (int i = 0; i < 4; i++) {
                int idx = i * 256 + tid;
                int m = idx >> 3, kq = idx & 7, kg = (c + 1) * 32 + kq * 4;
                float mn = Ms[m], rs = Rs[m];
                float4 v = ra[i];
                v.x = to_tf32((v.x - mn) * rs * g2s[kg] + bt2s[kg]);
                v.y = to_tf32((v.y - mn) * rs * g2s[kg + 1] + bt2s[kg + 1]);
                v.z = to_tf32((v.z - mn) * rs * g2s[kg + 2] + bt2s[kg + 2]);
                v.w = to_tf32((v.w - mn) * rs * g2s[kg + 3] + bt2s[kg + 3]);
                *(float4*)&As[m * 36 + kq * 4] = v;
                int kr = idx >> 5, nq = idx & 31;
                float4 w = rb[i];
                w.x = to_tf32(w.x); w.y = to_tf32(w.y); w.z = to_tf32(w.z); w.w = to_tf32(w.w);
                *(float4*)&Bs[kr * 132 + nq * 4] = w;
            }
        }
        __syncthreads();
    }

    #pragma unroll
    for (int mt = 0; mt < 2; mt++) {
        int r0 = m0 + wm * 32 + mt * 16 + gid;
        #pragma unroll
        for (int nt = 0; nt < 8; nt++) {
            int nl = wn * 64 + nt * 8 + 2 * tig;
            float t0 = acc[mt][nt][0] + biass[nl];
            float t1 = acc[mt][nt][1] + biass[nl + 1];
            float t2 = acc[mt][nt][2] + biass[nl];
            float t3 = acc[mt][nt][3] + biass[nl + 1];
            float o0 = 0.5f * t0 * (1.f + erff(t0 * 0.70710678118654752f));
            float o1 = 0.5f * t1 * (1.f + erff(t1 * 0.70710678118654752f));
            float o2 = 0.5f * t2 * (1.f + erff(t2 * 0.70710678118654752f));
            float o3 = 0.5f * t3 * (1.f + erff(t3 * 0.70710678118654752f));
            *(float2*)&g_h[(size_t)r0 * 1024 + n0 + nl] = make_float2(o0, o1);
            *(float2*)&g_h[(size_t)(r0 + 8) * 1024 + n0 + nl] = make_float2(o2, o3);
        }
    }
}

// -------------------------------------------------- MLP GEMM2 (tf32 mma.sync, +bias+residual, NCHW out)
__global__ void __launch_bounds__(256) mlp2_mma(
    const float* __restrict__ w2, const float* __restrict__ b2,
    float* __restrict__ out) {
    extern __shared__ __align__(16) float smf[];
    float* biass = smf + EXTOF;
    const int tid = threadIdx.x;
    const int wid = tid >> 5, lane = tid & 31;
    const int gid = lane >> 2, tig = lane & 3;
    const int wm = wid & 3, wn = wid >> 2;
    const int m0 = blockIdx.y * 128, n0 = blockIdx.x * 128;

    if (tid < 128) biass[tid] = b2[n0 + tid];
    __syncthreads();

    float acc[2][8][4] = {};
    float4 ra[4], rb[4];

    #pragma unroll
    for (int i = 0; i < 4; i++) {
        int idx = i * 256 + tid;
        ra[i] = *(const float4*)&g_h[(size_t)(m0 + (idx >> 3)) * 1024 + (idx & 7) * 4];
        rb[i] = *(const float4*)&w2[(size_t)(idx >> 5) * 256 + n0 + (idx & 31) * 4];
    }
    {
        float* As = smf; float* Bs = smf + 4608;
        #pragma unroll
        for (int i = 0; i < 4; i++) {
            int idx = i * 256 + tid;
            int m = idx >> 3, kq = idx & 7;
            float4 v = ra[i];
            v.x = to_tf32(v.x); v.y = to_tf32(v.y); v.z = to_tf32(v.z); v.w = to_tf32(v.w);
            *(float4*)&As[m * 36 + kq * 4] = v;
            int kr = idx >> 5, nq = idx & 31;
            float4 w = rb[i];
            w.x = to_tf32(w.x); w.y = to_tf32(w.y); w.z = to_tf32(w.z); w.w = to_tf32(w.w);
            *(float4*)&Bs[kr * 132 + nq * 4] = w;
        }
    }
    __syncthreads();

    for (int c = 0; c < 32; c++) {
        if (c + 1 < 32) {
            #pragma unroll
            for (int i = 0; i < 4; i++) {
                int idx = i * 256 + tid;
                ra[i] = *(const float4*)&g_h[(size_t)(m0 + (idx >> 3)) * 1024 + (c + 1) * 32 + (idx & 7) * 4];
                rb[i] = *(const float4*)&w2[(size_t)((c + 1) * 32 + (idx >> 5)) * 256 + n0 + (idx & 31) * 4];
            }
        }
        {
            const float* As = smf + (c & 1) * SBUF;
            mma_chunk(As, As + 4608, wm, wn, gid, tig, acc);
        }
        if (c + 1 < 32) {
            float* As = smf + ((c + 1) & 1) * SBUF;
            float* Bs = As + 4608;
            #pragma unroll
            for (int i = 0; i < 4; i++) {
                int idx = i * 256 + tid;
                int m = idx >> 3, kq = idx & 7;
                float4 v = ra[i];
                v.x = to_tf32(v.x); v.y = to_tf32(v.y); v.z = to_tf32(v.z); v.w = to_tf32(v.w);
                *(float4*)&As[m * 36 + kq * 4] = v;
                int kr = idx >> 5, nq = idx & 31;
                float4 w = rb[i];
                w.x = to_tf32(w.x); w.y = to_tf32(w.y); w.z = to_tf32(w.z); w.w = to_tf32(w.w);
                *(float4*)&Bs[kr * 132 + nq * 4] = w;
            }
        }
        __syncthreads();
    }

    float* Cs = smf;
    #pragma unroll
    for (int mt = 0; mt < 2; mt++) {
        int rm = wm * 32 + mt * 16 + gid;
        #pragma unroll
        for (int nt = 0; nt < 8; nt++) {
            int nl = wn * 64 + nt * 8 + 2 * tig;
            float2 r0 = *(const float2*)&g_y[(size_t)(m0 + rm) * 256 + n0 + nl];
            float2 r1 = *(const float2*)&g_y[(size_t)(m0 + rm + 8) * 256 + n0 + nl];
            Cs[nl * 132 + rm]           = acc[mt][nt][0] + biass[nl] + r0.x;
            Cs[(nl + 1) * 132 + rm]     = acc[mt][nt][1] + biass[nl + 1] + r0.y;
            Cs[nl * 132 + rm + 8]       = acc[mt][nt][2] + biass[nl] + r1.x;
            Cs[(nl + 1) * 132 + rm + 8] = acc[mt][nt][3] + biass[nl + 1] + r1.y;
        }
    }
    __syncthreads();
    {
        int n = tid >> 1, hf = tid & 1;
        #pragma unroll
        for (int j = 0; j < 16; j++) {
            float4 v = *(const float4*)&Cs[n * 132 + hf * 64 + j * 4];
            *(float4*)&out[(size_t)(n0 + n) * HW + m0 + hf * 64 + j * 4] = v;
        }
    }
}

extern "C" void kernel_launch(void* const* d_in, const int* in_sizes, int n_in,
                              void* d_out, int out_size) {
    const float* x       = (const float*)d_in[0];
    const float* norm1_g = (const float*)d_in[1];
    const float* norm1_b = (const float*)d_in[2];
    const float* qkv_r   = (const float*)d_in[3];
    const float* proj_rw = (const float*)d_in[4];
    const float* proj_rb = (const float*)d_in[5];
    const float* table_r = (const float*)d_in[6];
    const float* qkv_a   = (const float*)d_in[7];
    const float* proj_aw = (const float*)d_in[8];
    const float* proj_ab = (const float*)d_in[9];
    const float* table_a = (const float*)d_in[10];
    const float* norm2_g = (const float*)d_in[11];
    const float* norm2_b = (const float*)d_in[12];
    const float* mlp_w1  = (const float*)d_in[13];
    const float* mlp_b1  = (const float*)d_in[14];
    const float* mlp_w2  = (const float*)d_in[15];
    const float* mlp_b2  = (const float*)d_in[16];
    float* out = (float*)d_out;

    cudaFuncSetAttribute(ln1_kernel, cudaFuncAttributeMaxDynamicSharedMemorySize, LN1_SMEM);
    cudaFuncSetAttribute(attn_kernel, cudaFuncAttributeMaxDynamicSharedMemorySize, ATTN_SMEM);
    cudaFuncSetAttribute(resid_ln2_kernel, cudaFuncAttributeMaxDynamicSharedMemorySize, RES_SMEM);
    cudaFuncSetAttribute(mlp1_mma, cudaFuncAttributeMaxDynamicSharedMemorySize, MMA_SMEM);
    cudaFuncSetAttribute(mlp2_mma, cudaFuncAttributeMaxDynamicSharedMemorySize, MMA_SMEM);

    ln1_kernel<<<1024, 256, LN1_SMEM>>>(x, norm1_g, norm1_b);
    attn_kernel<<<dim3(1024, 2), 256, ATTN_SMEM>>>(qkv_r, proj_rw, proj_rb, table_r,
                                                   qkv_a, proj_aw, proj_ab, table_a);
    resid_ln2_kernel<<<1024, 256, RES_SMEM>>>(x);
    mlp1_mma<<<dim3(8, 512), 256, MMA_SMEM>>>(mlp_w1, mlp_b1, norm2_g, norm2_b);
    mlp2_mma<<<dim3(2, 512), 256, MMA_SMEM>>>(mlp_w2, mlp_b2, out);
}